// round 5
// baseline (speedup 1.0000x reference)
#include <cuda_runtime.h>

#define N_NODES 100000
#define DIM 64
#define R 5
#define E 500000
#define TILE_N 128
#define PAD 66  // x_sh row pitch in floats: odd*2 -> conflict-free LDS.64 d-pair loads

// Per-relation, per-direction transformed features: tmp[(r*2+dir)][n][o]. 256 MB.
__device__ __align__(16) float g_tmp[(size_t)R * 2 * N_NODES * DIM];
__device__ __align__(16) float g_Wc_u[R * DIM * DIM];
__device__ __align__(16) float g_Wc_v[R * DIM * DIM];

// ---------------------------------------------------------------------------
// out init: rows = bias (scatter adds on top, relu finishes in place).
// ---------------------------------------------------------------------------
__global__ void init_out_kernel(const float* __restrict__ bias_u,
                                const float* __restrict__ bias_v,
                                float* __restrict__ out) {
    const size_t n4 = (size_t)2 * N_NODES * (DIM / 4);
    float4* o4 = reinterpret_cast<float4*>(out);
    for (size_t i = (size_t)blockIdx.x * blockDim.x + threadIdx.x; i < n4;
         i += (size_t)gridDim.x * blockDim.x) {
        int c = (int)(i & 15);
        const float4* b = reinterpret_cast<const float4*>(
            i < (size_t)N_NODES * 16 ? bias_u : bias_v);
        o4[i] = __ldg(b + c);
    }
}

// ---------------------------------------------------------------------------
// Cumulative (ordinal mixture) weights: Wc[r] = sum_{j<=r} W[j].
// ---------------------------------------------------------------------------
__global__ void cumsum_kernel(const float* __restrict__ wu,
                              const float* __restrict__ wv) {
    int t = blockIdx.x * blockDim.x + threadIdx.x;
    if (t >= DIM * DIM) return;
    float a = 0.f, b = 0.f;
#pragma unroll
    for (int r = 0; r < R; r++) {
        a += wu[r * DIM * DIM + t];
        b += wv[r * DIM * DIM + t];
        g_Wc_u[r * DIM * DIM + t] = a;
        g_Wc_v[r * DIM * DIM + t] = b;
    }
}

// ---------------------------------------------------------------------------
// tmp GEMM, all relations: tmp[r,dir] = x_dir @ Wc_dir[r].
// Block 256 = 8 warps. Warp w owns outputs [w*8, w*8+8); lane owns 4 nodes
// (lane + j*32). x tile (128 x 64) staged ONCE, reused for all 5 relations.
// Accumulators f32x2 packed over d-pairs: weight pair {W[2dp][o],W[2dp+1][o]}
// staged contiguously (warp-broadcast LDS), x pair contiguous in x_sh row.
// acc = 4x8 f32x2 = 64 regs -> no spill (R3's 8x8 = 128 regs spilled).
// ---------------------------------------------------------------------------
__global__ __launch_bounds__(256) void tmp_gemm_kernel(
    const float* __restrict__ x_u, const float* __restrict__ x_v) {
    extern __shared__ float sh[];
    float* x_sh = sh;  // [TILE_N][PAD]
    unsigned long long* w_sh =
        reinterpret_cast<unsigned long long*>(sh + TILE_N * PAD);  // [32][64]

    const int dir = blockIdx.y;
    const float* __restrict__ X = dir ? x_v : x_u;
    const float* __restrict__ Wbase = dir ? g_Wc_v : g_Wc_u;

    const int nbase = blockIdx.x * TILE_N;
    const int tid = threadIdx.x;
    const int lane = tid & 31;
    const int wid = tid >> 5;
    const int o0 = wid * 8;

    // Stage x tile once (float2, coalesced, zero-padded past N_NODES).
    for (int i = tid; i < TILE_N * 32; i += 256) {
        int row = i >> 5, c = i & 31;
        int gn = nbase + row;
        float2 v = make_float2(0.f, 0.f);
        if (gn < N_NODES)
            v = reinterpret_cast<const float2*>(X + (size_t)gn * DIM)[c];
        *reinterpret_cast<float2*>(x_sh + row * PAD + c * 2) = v;
    }

    for (int r = 0; r < R; r++) {
        __syncthreads();
        // Stage weight d-pairs: w_sh[dp*64 + o] = {W[2dp][o], W[2dp+1][o]}.
        const float* W = Wbase + r * DIM * DIM;
        for (int i = tid; i < 32 * DIM; i += 256) {
            int dp = i >> 6, o = i & 63;
            float lo = W[(2 * dp) * DIM + o];
            float hi = W[(2 * dp + 1) * DIM + o];
            unsigned long long p;
            asm("mov.b64 %0, {%1,%2};" : "=l"(p) : "f"(lo), "f"(hi));
            w_sh[i] = p;
        }
        __syncthreads();

        unsigned long long acc[4][8];
#pragma unroll
        for (int j = 0; j < 4; j++)
#pragma unroll
            for (int k = 0; k < 8; k++) acc[j][k] = 0ull;

#pragma unroll 4
        for (int dp = 0; dp < 32; dp++) {
            unsigned long long w[8];
            const ulonglong2* wp =
                reinterpret_cast<const ulonglong2*>(w_sh + dp * DIM + o0);
#pragma unroll
            for (int k = 0; k < 4; k++) {  // warp-broadcast loads
                ulonglong2 t = wp[k];
                w[2 * k] = t.x;
                w[2 * k + 1] = t.y;
            }
#pragma unroll
            for (int j = 0; j < 4; j++) {
                unsigned long long s =
                    *reinterpret_cast<const unsigned long long*>(
                        x_sh + (lane + j * 32) * PAD + dp * 2);
#pragma unroll
                for (int k = 0; k < 8; k++)
                    asm("fma.rn.f32x2 %0, %1, %2, %0;"
                        : "+l"(acc[j][k])
                        : "l"(s), "l"(w[k]));
            }
        }

        float* T = g_tmp + ((size_t)(r * 2 + dir) * N_NODES) * DIM;
#pragma unroll
        for (int j = 0; j < 4; j++) {
            int gn = nbase + lane + j * 32;
            if (gn >= N_NODES) continue;
            float res[8];
#pragma unroll
            for (int k = 0; k < 8; k++) {
                float lo, hi;
                asm("mov.b64 {%0,%1}, %2;" : "=f"(lo), "=f"(hi) : "l"(acc[j][k]));
                res[k] = lo + hi;
            }
            float4* op = reinterpret_cast<float4*>(T + (size_t)gn * DIM + o0);
            op[0] = make_float4(res[0], res[1], res[2], res[3]);
            op[1] = make_float4(res[4], res[5], res[6], res[7]);
        }
    }
}

// ---------------------------------------------------------------------------
// Merged edge scatter: one warp per (edge, relation), both directions.
// lanes 0-15 : out_u[edge_u] += val * tmp[r,v][edge_v]  (red.global.add.v4)
// lanes 16-31: out_v[edge_v] += val * tmp[r,u][edge_u]
// ---------------------------------------------------------------------------
__global__ __launch_bounds__(256) void scatter_kernel(
    const float* __restrict__ edge_val, const int* __restrict__ edge_u,
    const int* __restrict__ edge_v, float* __restrict__ out) {
    long gw = ((long)blockIdx.x * blockDim.x + threadIdx.x) >> 5;
    if (gw >= (long)R * E) return;
    const int lane = threadIdx.x & 31;

    const float val = __ldg(edge_val + gw);
    const int u = __ldg(edge_u + gw);
    const int v = __ldg(edge_v + gw);
    const int r = (int)(gw / E);
    const int q = lane & 15;

    const float* src;
    float* dst;
    if (lane < 16) {
        src = g_tmp + ((size_t)(r * 2 + 1) * N_NODES + v) * DIM;  // tmp_v
        dst = out + (size_t)u * DIM;
    } else {
        src = g_tmp + ((size_t)(r * 2 + 0) * N_NODES + u) * DIM;  // tmp_u
        dst = out + ((size_t)N_NODES + v) * DIM;
    }

    float4 p = *reinterpret_cast<const float4*>(src + q * 4);
    p.x *= val;
    p.y *= val;
    p.z *= val;
    p.w *= val;
    asm volatile("red.global.add.v4.f32 [%0], {%1,%2,%3,%4};" ::"l"(dst + q * 4),
                 "f"(p.x), "f"(p.y), "f"(p.z), "f"(p.w)
                 : "memory");
}

// ---------------------------------------------------------------------------
// Final ReLU in place on out.
// ---------------------------------------------------------------------------
__global__ void relu_kernel(float* __restrict__ out) {
    const size_t n4 = (size_t)2 * N_NODES * (DIM / 4);
    float4* o4 = reinterpret_cast<float4*>(out);
    for (size_t i = (size_t)blockIdx.x * blockDim.x + threadIdx.x; i < n4;
         i += (size_t)gridDim.x * blockDim.x) {
        float4 v = o4[i];
        v.x = v.x > 0.f ? v.x : 0.f;
        v.y = v.y > 0.f ? v.y : 0.f;
        v.z = v.z > 0.f ? v.z : 0.f;
        v.w = v.w > 0.f ? v.w : 0.f;
        o4[i] = v;
    }
}

// ---------------------------------------------------------------------------
extern "C" void kernel_launch(void* const* d_in, const int* in_sizes, int n_in,
                              void* d_out, int out_size) {
    const float* x_u = (const float*)d_in[0];
    const float* x_v = (const float*)d_in[1];
    const float* w_u = (const float*)d_in[2];
    const float* w_v = (const float*)d_in[3];
    const float* bias_u = (const float*)d_in[4];
    const float* bias_v = (const float*)d_in[5];
    const float* edge_val = (const float*)d_in[6];
    const int* edge_u = (const int*)d_in[7];
    const int* edge_v = (const int*)d_in[8];
    float* out = (float*)d_out;

    const int smem_bytes = TILE_N * PAD * 4 + 32 * DIM * 8;  // ~49.8 KB
    static int attr_set = 0;
    if (!attr_set) {
        cudaFuncSetAttribute(tmp_gemm_kernel,
                             cudaFuncAttributeMaxDynamicSharedMemorySize,
                             smem_bytes);
        attr_set = 1;
    }

    init_out_kernel<<<2048, 256>>>(bias_u, bias_v, out);
    cumsum_kernel<<<16, 256>>>(w_u, w_v);

    dim3 ggrid((N_NODES + TILE_N - 1) / TILE_N, 2);
    tmp_gemm_kernel<<<ggrid, 256, smem_bytes>>>(x_u, x_v);

    const int sblocks = (int)(((long)R * E * 32 + 255) / 256);  // 312500
    scatter_kernel<<<sblocks, 256>>>(edge_val, edge_u, edge_v, out);

    relu_kernel<<<2048, 256>>>(out);
}

// round 6
// speedup vs baseline: 1.0136x; 1.0136x over previous
#include <cuda_runtime.h>

#define N_NODES 100000
#define DIM 64
#define R 5
#define E 500000
#define TILE_N 128
#define PAD 66  // x_sh row pitch in floats: odd*2 -> conflict-free LDS.64 d-pair loads

// Per-relation, per-direction transformed features: tmp[(r*2+dir)][n][o]. 256 MB.
__device__ __align__(16) float g_tmp[(size_t)R * 2 * N_NODES * DIM];
__device__ __align__(16) float g_Wc_u[R * DIM * DIM];
__device__ __align__(16) float g_Wc_v[R * DIM * DIM];

// ---------------------------------------------------------------------------
// out init: rows = bias (scatter adds on top, relu finishes in place).
// ---------------------------------------------------------------------------
__global__ void init_out_kernel(const float* __restrict__ bias_u,
                                const float* __restrict__ bias_v,
                                float* __restrict__ out) {
    const size_t n4 = (size_t)2 * N_NODES * (DIM / 4);
    float4* o4 = reinterpret_cast<float4*>(out);
    for (size_t i = (size_t)blockIdx.x * blockDim.x + threadIdx.x; i < n4;
         i += (size_t)gridDim.x * blockDim.x) {
        int c = (int)(i & 15);
        const float4* b = reinterpret_cast<const float4*>(
            i < (size_t)N_NODES * 16 ? bias_u : bias_v);
        o4[i] = __ldg(b + c);
    }
}

// ---------------------------------------------------------------------------
// Cumulative (ordinal mixture) weights: Wc[r] = sum_{j<=r} W[j].
// ---------------------------------------------------------------------------
__global__ void cumsum_kernel(const float* __restrict__ wu,
                              const float* __restrict__ wv) {
    int t = blockIdx.x * blockDim.x + threadIdx.x;
    if (t >= DIM * DIM) return;
    float a = 0.f, b = 0.f;
#pragma unroll
    for (int r = 0; r < R; r++) {
        a += wu[r * DIM * DIM + t];
        b += wv[r * DIM * DIM + t];
        g_Wc_u[r * DIM * DIM + t] = a;
        g_Wc_v[r * DIM * DIM + t] = b;
    }
}

// ---------------------------------------------------------------------------
// tmp GEMM, all relations: tmp[r,dir] = x_dir @ Wc_dir[r].
// Block 256 = 8 warps. Warp w owns outputs [w*8, w*8+8); lane owns 4 nodes
// (lane + j*32). x tile (128 x 64) staged ONCE, reused for all 5 relations.
// Accumulators f32x2 packed over d-pairs: weight pair {W[2dp][o],W[2dp+1][o]}
// staged contiguously (warp-broadcast LDS), x pair contiguous in x_sh row.
// acc = 4x8 f32x2 = 64 regs -> no spill (R3's 8x8 = 128 regs spilled).
// ---------------------------------------------------------------------------
__global__ __launch_bounds__(256) void tmp_gemm_kernel(
    const float* __restrict__ x_u, const float* __restrict__ x_v) {
    extern __shared__ float sh[];
    float* x_sh = sh;  // [TILE_N][PAD]
    unsigned long long* w_sh =
        reinterpret_cast<unsigned long long*>(sh + TILE_N * PAD);  // [32][64]

    const int dir = blockIdx.y;
    const float* __restrict__ X = dir ? x_v : x_u;
    const float* __restrict__ Wbase = dir ? g_Wc_v : g_Wc_u;

    const int nbase = blockIdx.x * TILE_N;
    const int tid = threadIdx.x;
    const int lane = tid & 31;
    const int wid = tid >> 5;
    const int o0 = wid * 8;

    // Stage x tile once (float2, coalesced, zero-padded past N_NODES).
    for (int i = tid; i < TILE_N * 32; i += 256) {
        int row = i >> 5, c = i & 31;
        int gn = nbase + row;
        float2 v = make_float2(0.f, 0.f);
        if (gn < N_NODES)
            v = reinterpret_cast<const float2*>(X + (size_t)gn * DIM)[c];
        *reinterpret_cast<float2*>(x_sh + row * PAD + c * 2) = v;
    }

    for (int r = 0; r < R; r++) {
        __syncthreads();
        // Stage weight d-pairs: w_sh[dp*64 + o] = {W[2dp][o], W[2dp+1][o]}.
        const float* W = Wbase + r * DIM * DIM;
        for (int i = tid; i < 32 * DIM; i += 256) {
            int dp = i >> 6, o = i & 63;
            float lo = W[(2 * dp) * DIM + o];
            float hi = W[(2 * dp + 1) * DIM + o];
            unsigned long long p;
            asm("mov.b64 %0, {%1,%2};" : "=l"(p) : "f"(lo), "f"(hi));
            w_sh[i] = p;
        }
        __syncthreads();

        unsigned long long acc[4][8];
#pragma unroll
        for (int j = 0; j < 4; j++)
#pragma unroll
            for (int k = 0; k < 8; k++) acc[j][k] = 0ull;

#pragma unroll 4
        for (int dp = 0; dp < 32; dp++) {
            unsigned long long w[8];
            const ulonglong2* wp =
                reinterpret_cast<const ulonglong2*>(w_sh + dp * DIM + o0);
#pragma unroll
            for (int k = 0; k < 4; k++) {  // warp-broadcast loads
                ulonglong2 t = wp[k];
                w[2 * k] = t.x;
                w[2 * k + 1] = t.y;
            }
#pragma unroll
            for (int j = 0; j < 4; j++) {
                unsigned long long s =
                    *reinterpret_cast<const unsigned long long*>(
                        x_sh + (lane + j * 32) * PAD + dp * 2);
#pragma unroll
                for (int k = 0; k < 8; k++)
                    asm("fma.rn.f32x2 %0, %1, %2, %0;"
                        : "+l"(acc[j][k])
                        : "l"(s), "l"(w[k]));
            }
        }

        float* T = g_tmp + ((size_t)(r * 2 + dir) * N_NODES) * DIM;
#pragma unroll
        for (int j = 0; j < 4; j++) {
            int gn = nbase + lane + j * 32;
            if (gn >= N_NODES) continue;
            float res[8];
#pragma unroll
            for (int k = 0; k < 8; k++) {
                float lo, hi;
                asm("mov.b64 {%0,%1}, %2;" : "=f"(lo), "=f"(hi) : "l"(acc[j][k]));
                res[k] = lo + hi;
            }
            float4* op = reinterpret_cast<float4*>(T + (size_t)gn * DIM + o0);
            op[0] = make_float4(res[0], res[1], res[2], res[3]);
            op[1] = make_float4(res[4], res[5], res[6], res[7]);
        }
    }
}

// ---------------------------------------------------------------------------
// Merged edge scatter: one warp per (edge, relation), both directions.
// lanes 0-15 : out_u[edge_u] += val * tmp[r,v][edge_v]  (red.global.add.v4)
// lanes 16-31: out_v[edge_v] += val * tmp[r,u][edge_u]
// ---------------------------------------------------------------------------
__global__ __launch_bounds__(256) void scatter_kernel(
    const float* __restrict__ edge_val, const int* __restrict__ edge_u,
    const int* __restrict__ edge_v, float* __restrict__ out) {
    long gw = ((long)blockIdx.x * blockDim.x + threadIdx.x) >> 5;
    if (gw >= (long)R * E) return;
    const int lane = threadIdx.x & 31;

    const float val = __ldg(edge_val + gw);
    const int u = __ldg(edge_u + gw);
    const int v = __ldg(edge_v + gw);
    const int r = (int)(gw / E);
    const int q = lane & 15;

    const float* src;
    float* dst;
    if (lane < 16) {
        src = g_tmp + ((size_t)(r * 2 + 1) * N_NODES + v) * DIM;  // tmp_v
        dst = out + (size_t)u * DIM;
    } else {
        src = g_tmp + ((size_t)(r * 2 + 0) * N_NODES + u) * DIM;  // tmp_u
        dst = out + ((size_t)N_NODES + v) * DIM;
    }

    float4 p = *reinterpret_cast<const float4*>(src + q * 4);
    p.x *= val;
    p.y *= val;
    p.z *= val;
    p.w *= val;
    asm volatile("red.global.add.v4.f32 [%0], {%1,%2,%3,%4};" ::"l"(dst + q * 4),
                 "f"(p.x), "f"(p.y), "f"(p.z), "f"(p.w)
                 : "memory");
}

// ---------------------------------------------------------------------------
// Final ReLU in place on out.
// ---------------------------------------------------------------------------
__global__ void relu_kernel(float* __restrict__ out) {
    const size_t n4 = (size_t)2 * N_NODES * (DIM / 4);
    float4* o4 = reinterpret_cast<float4*>(out);
    for (size_t i = (size_t)blockIdx.x * blockDim.x + threadIdx.x; i < n4;
         i += (size_t)gridDim.x * blockDim.x) {
        float4 v = o4[i];
        v.x = v.x > 0.f ? v.x : 0.f;
        v.y = v.y > 0.f ? v.y : 0.f;
        v.z = v.z > 0.f ? v.z : 0.f;
        v.w = v.w > 0.f ? v.w : 0.f;
        o4[i] = v;
    }
}

// ---------------------------------------------------------------------------
extern "C" void kernel_launch(void* const* d_in, const int* in_sizes, int n_in,
                              void* d_out, int out_size) {
    const float* x_u = (const float*)d_in[0];
    const float* x_v = (const float*)d_in[1];
    const float* w_u = (const float*)d_in[2];
    const float* w_v = (const float*)d_in[3];
    const float* bias_u = (const float*)d_in[4];
    const float* bias_v = (const float*)d_in[5];
    const float* edge_val = (const float*)d_in[6];
    const int* edge_u = (const int*)d_in[7];
    const int* edge_v = (const int*)d_in[8];
    float* out = (float*)d_out;

    const int smem_bytes = TILE_N * PAD * 4 + 32 * DIM * 8;  // ~49.8 KB
    static int attr_set = 0;
    if (!attr_set) {
        cudaFuncSetAttribute(tmp_gemm_kernel,
                             cudaFuncAttributeMaxDynamicSharedMemorySize,
                             smem_bytes);
        attr_set = 1;
    }

    init_out_kernel<<<2048, 256>>>(bias_u, bias_v, out);
    cumsum_kernel<<<16, 256>>>(w_u, w_v);

    dim3 ggrid((N_NODES + TILE_N - 1) / TILE_N, 2);
    tmp_gemm_kernel<<<ggrid, 256, smem_bytes>>>(x_u, x_v);

    const int sblocks = (int)(((long)R * E * 32 + 255) / 256);  // 312500
    scatter_kernel<<<sblocks, 256>>>(edge_val, edge_u, edge_v, out);

    relu_kernel<<<2048, 256>>>(out);
}